// round 3
// baseline (speedup 1.0000x reference)
#include <cuda_runtime.h>
#include <math.h>

#define H     1024
#define H4    256            // float4 per H row
#define HH2   512
#define V     32000
#define WIN   129
#define NB    444            // 3 CTAs/SM x 148 SMs — single co-resident wave
#define NT    512
#define NWARP 16
#define NWRP  (NB * NWARP)   // 7104 warps
#define SMAX  4096
#define NEG   -1e30f

// ---------------- persistent scratch (no allocation allowed) ----------------
__device__ float g_t1[HH2];          // tanh(att_fc1)
__device__ float g_sc[SMAX];         // full-sequence raw scores
__device__ float g_ctx[H];           // attention context (atomicAdd target)
__device__ float g_pm[NB];           // per-block logit max
__device__ float g_ps[NB];           // per-block logit expsum (rel. to g_pm)
__device__ unsigned g_cnt;
__device__ volatile unsigned g_sense;

// ---------------- helpers ----------------
__device__ __forceinline__ float dot4(float4 a, float4 b) {
    return fmaf(a.x, b.x, fmaf(a.y, b.y, fmaf(a.z, b.z, a.w * b.w)));
}
__device__ __forceinline__ float warpSum(float v) {
    #pragma unroll
    for (int o = 16; o > 0; o >>= 1) v += __shfl_xor_sync(0xffffffffu, v, o);
    return v;
}
__device__ __forceinline__ float warpMax(float v) {
    #pragma unroll
    for (int o = 16; o > 0; o >>= 1) v = fmaxf(v, __shfl_xor_sync(0xffffffffu, v, o));
    return v;
}
__device__ __forceinline__ float sigm(float x) { return 1.f / (1.f + expf(-x)); }

// ---------------- grid barrier (sense-reversing, NB blocks) ----------------
__device__ __forceinline__ void gbar() {
    __syncthreads();
    if (threadIdx.x == 0) {
        unsigned my = g_sense;
        __threadfence();
        if (atomicAdd(&g_cnt, 1u) == NB - 1u) {
            atomicExch(&g_cnt, 0u);
            __threadfence();
            g_sense = my ^ 1u;
        } else {
            while (g_sense == my) __nanosleep(32);
            __threadfence();
        }
    }
    __syncthreads();
}

struct Shm {
    float4 xv[H4];      // 4KB: x / h_t / fco vector
    float4 hv[H4];      // 4KB: h_prev vector
    float  gate[NWARP];
    float  red[NWARP];
    float  sarr[WIN];
    float  aarr[WIN];
    float  mr[512];
    float  sr[512];
    float  p; int ws, we; float mx, sum;
};

// ---------------- LSTM layer: nu units/block, 4 gate-warps per unit ----------------
__device__ __forceinline__ void lstm_layer(
    const float* __restrict__ cprev,
    const float* __restrict__ wih, const float* __restrict__ whh,
    const float* __restrict__ bih, const float* __restrict__ bhh,
    float* __restrict__ hout, float* __restrict__ cout,
    int bid, int wid, int lane, int tid, Shm& sm)
{
    int u0 = (bid * H) / NB;
    int u1 = ((bid + 1) * H) / NB;
    int nu = u1 - u0;                    // 2 or 3
    int q = wid >> 2, g = wid & 3;
    if (q < nu) {
        int row = g * H + u0 + q;
        const float4* wi = (const float4*)wih + (size_t)row * H4;
        const float4* wh = (const float4*)whh + (size_t)row * H4;
        float acc = 0.f;
        for (int k = 0; k < 8; k++) {
            int i = lane + 32 * k;
            acc += dot4(wi[i], sm.xv[i]) + dot4(wh[i], sm.hv[i]);
        }
        acc = warpSum(acc);
        if (lane == 0) sm.gate[wid] = acc;
    }
    __syncthreads();
    if (tid < nu) {
        int u = u0 + tid;
        float gi = sm.gate[tid * 4 + 0] + bih[u        ] + bhh[u        ];
        float gf = sm.gate[tid * 4 + 1] + bih[u +     H] + bhh[u +     H];
        float gg = sm.gate[tid * 4 + 2] + bih[u + 2 * H] + bhh[u + 2 * H];
        float go = sm.gate[tid * 4 + 3] + bih[u + 3 * H] + bhh[u + 3 * H];
        float c  = sigm(gf) * cprev[u] + sigm(gi) * tanhf(gg);
        cout[u] = c;
        hout[u] = sigm(go) * tanhf(c);
    }
}

// ---------------- the megakernel ----------------
__global__ void __launch_bounds__(NT, 3) decoder_mega(
    const float* __restrict__ enc, const int* __restrict__ word,
    const float* __restrict__ h0,  const float* __restrict__ c0,
    const float* __restrict__ emb,
    const float* __restrict__ wih, const float* __restrict__ whh,
    const float* __restrict__ bih, const float* __restrict__ bhh,
    const float* __restrict__ a1w, const float* __restrict__ a1b,
    const float* __restrict__ a2w, const float* __restrict__ a2b,
    const float* __restrict__ f1w, const float* __restrict__ f1b,
    const float* __restrict__ f2w, const float* __restrict__ f2b,
    float* __restrict__ dout, int S)
{
    __shared__ Shm sm;
    const int tid = threadIdx.x, lane = tid & 31, wid = tid >> 5;
    const int bid = blockIdx.x;
    const int gw  = bid * NWARP + wid;
    const float Sf = (float)S;

    float* y    = dout;
    float* fco  = y   + V;
    float* hn   = fco + H;
    float* cn   = hn  + 2 * H;
    float* aout = cn  + 2 * H;

    // ---- phase 0: LSTM layer 0 ----
    if (tid < 256) sm.xv[tid]       = ((const float4*)(emb + (size_t)word[0] * H))[tid];
    else           sm.hv[tid - 256] = ((const float4*)h0)[tid - 256];
    __syncthreads();
    lstm_layer(c0, wih, whh, bih, bhh, hn, cn, bid, wid, lane, tid, sm);
    gbar();

    // ---- phase 1: LSTM layer 1 ----
    if (tid < 256) sm.xv[tid]       = ((const float4*)hn)[tid];
    else           sm.hv[tid - 256] = ((const float4*)(h0 + H))[tid - 256];
    __syncthreads();
    lstm_layer(c0 + H, wih + 4 * H * H, whh + 4 * H * H,
               bih + 4 * H, bhh + 4 * H, hn + H, cn + H, bid, wid, lane, tid, sm);
    gbar();

    // ---- phase 2: att_fc1 + full-sequence scores + ctx reset (ht -> sm.xv) ----
    if (tid < 256) sm.xv[tid] = ((const float4*)(hn + H))[tid];
    __syncthreads();
    if (gw < HH2) {
        const float4* w4 = (const float4*)a1w + (size_t)gw * H4;
        float acc = 0.f;
        for (int k = 0; k < 8; k++) { int i = lane + 32 * k; acc += dot4(w4[i], sm.xv[i]); }
        acc = warpSum(acc);
        if (lane == 0) g_t1[gw] = tanhf(acc + a1b[gw]);
    } else {
        int s = gw - HH2;
        int slim = (S < SMAX) ? S : SMAX;
        if (s < slim) {
            const float4* e4 = (const float4*)(enc + (size_t)s * H);
            float acc = 0.f;
            for (int k = 0; k < 8; k++) { int i = lane + 32 * k; acc += dot4(e4[i], sm.xv[i]); }
            acc = warpSum(acc);
            if (lane == 0) g_sc[s] = acc;
        }
    }
    if (bid == NB - 1) { g_ctx[tid] = 0.f; g_ctx[tid + 512] = 0.f; }
    gbar();

    // ---- phase 3: redundant p + window softmax; distributed ctx ----
    {
        float part = g_t1[tid < HH2 ? tid : 0] * a2w[tid < HH2 ? tid : 0];
        if (tid >= HH2) part = 0.f;     // NT==512 so all active, but keep safe
        part = warpSum(part);
        if (lane == 0) sm.red[wid] = part;
        __syncthreads();
        if (tid == 0) {
            float s = a2b[0];
            #pragma unroll
            for (int i = 0; i < NWARP; i++) s += sm.red[i];
            float p = Sf * sigm(s);
            sm.p  = p;
            sm.ws = (int)rintf(fmaxf(p - 64.f, 0.f));
            sm.we = (int)rintf(fminf(p + 64.f, Sf - 1.f));
        }
        __syncthreads();
        int ws = sm.ws, we = sm.we;
        if (tid < WIN) {
            int idx = ws + tid;
            sm.sarr[tid] = (idx <= we) ? g_sc[min(idx, S - 1)] : NEG;
        }
        __syncthreads();
        if (tid < 32) {
            float m = NEG;
            for (int i = lane; i < WIN; i += 32) m = fmaxf(m, sm.sarr[i]);
            m = warpMax(m);
            float e = 0.f;
            for (int i = lane; i < WIN; i += 32) e += expf(sm.sarr[i] - m);
            e = warpSum(e);
            if (lane == 0) { sm.mx = m; sm.sum = e; }
        }
        __syncthreads();
        if (tid < WIN) {
            int idx = ws + tid;
            float a = expf(sm.sarr[tid] - sm.mx) / sm.sum;
            float gs = expf(((float)idx - sm.p) * (1.f / 2048.f));
            a = (idx <= we) ? a * gs : 0.f;
            sm.aarr[tid] = a;
            if (bid == 0) aout[tid] = a;
        }
        __syncthreads();
        if (bid < WIN) {
            float a = sm.aarr[bid];
            int idx = min(sm.ws + bid, S - 1);
            const float* er = enc + (size_t)idx * H;
            atomicAdd(&g_ctx[tid      ], a * er[tid      ]);
            atomicAdd(&g_ctx[tid + 512], a * er[tid + 512]);
        }
    }
    gbar();

    // ---- phase 4: fc1 (1024 rows x 2048), rows spread over blocks ----
    {
        int r = wid * NB + bid;
        if (r < H) {
            const float4* w4 = (const float4*)f1w + (size_t)r * (2 * H4);
            const float4* c4 = (const float4*)g_ctx;
            float acc = 0.f;
            for (int k = 0; k < 8; k++) { int i = lane + 32 * k; acc += dot4(w4[i      ], c4[i]); }
            for (int k = 0; k < 8; k++) { int i = lane + 32 * k; acc += dot4(w4[i + 256], sm.xv[i]); }
            acc = warpSum(acc);
            if (lane == 0) fco[r] = tanhf(acc + f1b[r]);
        }
    }
    gbar();

    // ---- phase 5: fc2 (32000 x 1024) + online block-partial (max, expsum) ----
    {
        if (tid < 256) sm.xv[tid] = ((const float4*)fco)[tid];
        __syncthreads();
        float mw = NEG, sw = 0.f;
        for (int r = gw; r < V; r += NWRP) {
            const float4* w4 = (const float4*)f2w + (size_t)r * H4;
            float acc = 0.f;
            for (int k = 0; k < 8; k++) { int i = lane + 32 * k; acc += dot4(w4[i], sm.xv[i]); }
            acc = warpSum(acc);
            if (lane == 0) {
                float v = acc + f2b[r];
                y[r] = v;
                float m2 = fmaxf(mw, v);
                sw = sw * expf(mw - m2) + expf(v - m2);
                mw = m2;
            }
        }
        if (lane == 0) { sm.mr[wid] = mw; sm.sr[wid] = sw; }
        __syncthreads();
        if (tid == 0) {
            float M = NEG, Ss = 0.f;
            #pragma unroll
            for (int i = 0; i < NWARP; i++) {
                float m2 = fmaxf(M, sm.mr[i]);
                Ss = Ss * expf(M - m2) + sm.sr[i] * expf(sm.mr[i] - m2);
                M = m2;
            }
            g_pm[bid] = M; g_ps[bid] = Ss;
        }
    }
    gbar();

    // ---- phase 6: combine block partials (fixed tree), subtract lse ----
    {
        if (tid < NB) { sm.mr[tid] = g_pm[tid]; sm.sr[tid] = g_ps[tid]; }
        else          { sm.mr[tid] = NEG;       sm.sr[tid] = 0.f; }
        __syncthreads();
        for (int off = 256; off > 0; off >>= 1) {
            if (tid < off) {
                float m1 = sm.mr[tid], m2 = sm.mr[tid + off];
                float m = fmaxf(m1, m2);
                sm.sr[tid] = sm.sr[tid] * expf(m1 - m) + sm.sr[tid + off] * expf(m2 - m);
                sm.mr[tid] = m;
            }
            __syncthreads();
        }
        float lse = sm.mr[0] + logf(sm.sr[0]);
        const int chunk = (V + NB - 1) / NB;    // 73
        int i = bid * chunk + tid;
        if (tid < chunk && i < V) y[i] -= lse;
    }
}

// ---------------- launch ----------------
extern "C" void kernel_launch(void* const* d_in, const int* in_sizes, int n_in,
                              void* d_out, int out_size)
{
    const float* enc  = (const float*)d_in[1];
    const int*   word = (const int*)  d_in[2];
    const float* h0   = (const float*)d_in[3];
    const float* c0   = (const float*)d_in[4];
    const float* emb  = (const float*)d_in[5];
    const float* wih  = (const float*)d_in[6];
    const float* whh  = (const float*)d_in[7];
    const float* bih  = (const float*)d_in[8];
    const float* bhh  = (const float*)d_in[9];
    const float* a1w  = (const float*)d_in[10];
    const float* a1b  = (const float*)d_in[11];
    const float* a2w  = (const float*)d_in[12];
    const float* a2b  = (const float*)d_in[13];
    const float* f1w  = (const float*)d_in[14];
    const float* f1b  = (const float*)d_in[15];
    const float* f2w  = (const float*)d_in[16];
    const float* f2b  = (const float*)d_in[17];

    int S = in_sizes[1] / H;

    decoder_mega<<<NB, NT>>>(enc, word, h0, c0, emb, wih, whh, bih, bhh,
                             a1w, a1b, a2w, a2b, f1w, f1b, f2w, f2b,
                             (float*)d_out, S);
}

// round 4
// speedup vs baseline: 1.0004x; 1.0004x over previous
#include <cuda_runtime.h>
#include <math.h>

#define H     1024
#define H4    256            // float4 per H row
#define HH2   512
#define V     32000
#define WIN   129
#define NB    444            // 3 CTAs/SM x 148 SMs — single co-resident wave
#define NT    512
#define NWARP 16
#define NWRP  (NB * NWARP)   // 7104 warps
#define SMAX  4096
#define NEG   -1e30f

// ---------------- persistent scratch (no allocation allowed) ----------------
__device__ float g_t1[HH2];          // tanh(att_fc1)
__device__ float g_sc[SMAX];         // full-sequence raw scores
__device__ float g_ctx[H];           // attention context (atomicAdd target)
__device__ float g_pm[NB];           // per-block logit max
__device__ float g_ps[NB];           // per-block logit expsum (rel. to g_pm)
__device__ unsigned g_cnt;
__device__ volatile unsigned g_sense;

// ---------------- helpers ----------------
__device__ __forceinline__ float dot4(float4 a, float4 b) {
    return fmaf(a.x, b.x, fmaf(a.y, b.y, fmaf(a.z, b.z, a.w * b.w)));
}
__device__ __forceinline__ float warpSum(float v) {
    #pragma unroll
    for (int o = 16; o > 0; o >>= 1) v += __shfl_xor_sync(0xffffffffu, v, o);
    return v;
}
__device__ __forceinline__ float warpMax(float v) {
    #pragma unroll
    for (int o = 16; o > 0; o >>= 1) v = fmaxf(v, __shfl_xor_sync(0xffffffffu, v, o));
    return v;
}
__device__ __forceinline__ float sigm(float x) { return 1.f / (1.f + expf(-x)); }

// ---------------- grid barrier (sense-reversing, NB blocks) ----------------
__device__ __forceinline__ void gbar() {
    __syncthreads();
    if (threadIdx.x == 0) {
        unsigned my = g_sense;
        __threadfence();
        if (atomicAdd(&g_cnt, 1u) == NB - 1u) {
            atomicExch(&g_cnt, 0u);
            __threadfence();
            g_sense = my ^ 1u;
        } else {
            while (g_sense == my) __nanosleep(32);
            __threadfence();
        }
    }
    __syncthreads();
}

struct Shm {
    float4 xv[H4];      // 4KB: x / h_t / fco vector
    float4 hv[H4];      // 4KB: h_prev vector
    float  gate[NWARP];
    float  red[NWARP];
    float  sarr[WIN];
    float  aarr[WIN];
    float  mr[512];
    float  sr[512];
    float  p; int ws, we; float mx, sum;
};

// ---------------- LSTM layer: nu units/block, 4 gate-warps per unit ----------------
__device__ __forceinline__ void lstm_layer(
    const float* __restrict__ cprev,
    const float* __restrict__ wih, const float* __restrict__ whh,
    const float* __restrict__ bih, const float* __restrict__ bhh,
    float* __restrict__ hout, float* __restrict__ cout,
    int bid, int wid, int lane, int tid, Shm& sm)
{
    int u0 = (bid * H) / NB;
    int u1 = ((bid + 1) * H) / NB;
    int nu = u1 - u0;                    // 2 or 3
    int q = wid >> 2, g = wid & 3;
    if (q < nu) {
        int row = g * H + u0 + q;
        const float4* wi = (const float4*)wih + (size_t)row * H4;
        const float4* wh = (const float4*)whh + (size_t)row * H4;
        float acc = 0.f;
        for (int k = 0; k < 8; k++) {
            int i = lane + 32 * k;
            acc += dot4(wi[i], sm.xv[i]) + dot4(wh[i], sm.hv[i]);
        }
        acc = warpSum(acc);
        if (lane == 0) sm.gate[wid] = acc;
    }
    __syncthreads();
    if (tid < nu) {
        int u = u0 + tid;
        float gi = sm.gate[tid * 4 + 0] + bih[u        ] + bhh[u        ];
        float gf = sm.gate[tid * 4 + 1] + bih[u +     H] + bhh[u +     H];
        float gg = sm.gate[tid * 4 + 2] + bih[u + 2 * H] + bhh[u + 2 * H];
        float go = sm.gate[tid * 4 + 3] + bih[u + 3 * H] + bhh[u + 3 * H];
        float c  = sigm(gf) * cprev[u] + sigm(gi) * tanhf(gg);
        cout[u] = c;
        hout[u] = sigm(go) * tanhf(c);
    }
}

// ---------------- the megakernel ----------------
__global__ void __launch_bounds__(NT, 3) decoder_mega(
    const float* __restrict__ enc, const int* __restrict__ word,
    const float* __restrict__ h0,  const float* __restrict__ c0,
    const float* __restrict__ emb,
    const float* __restrict__ wih, const float* __restrict__ whh,
    const float* __restrict__ bih, const float* __restrict__ bhh,
    const float* __restrict__ a1w, const float* __restrict__ a1b,
    const float* __restrict__ a2w, const float* __restrict__ a2b,
    const float* __restrict__ f1w, const float* __restrict__ f1b,
    const float* __restrict__ f2w, const float* __restrict__ f2b,
    float* __restrict__ dout, int S)
{
    __shared__ Shm sm;
    const int tid = threadIdx.x, lane = tid & 31, wid = tid >> 5;
    const int bid = blockIdx.x;
    const int gw  = bid * NWARP + wid;
    const float Sf = (float)S;

    float* y    = dout;
    float* fco  = y   + V;
    float* hn   = fco + H;
    float* cn   = hn  + 2 * H;
    float* aout = cn  + 2 * H;

    // ---- phase 0: LSTM layer 0 ----
    if (tid < 256) sm.xv[tid]       = ((const float4*)(emb + (size_t)word[0] * H))[tid];
    else           sm.hv[tid - 256] = ((const float4*)h0)[tid - 256];
    __syncthreads();
    lstm_layer(c0, wih, whh, bih, bhh, hn, cn, bid, wid, lane, tid, sm);
    gbar();

    // ---- phase 1: LSTM layer 1 ----
    if (tid < 256) sm.xv[tid]       = ((const float4*)hn)[tid];
    else           sm.hv[tid - 256] = ((const float4*)(h0 + H))[tid - 256];
    __syncthreads();
    lstm_layer(c0 + H, wih + 4 * H * H, whh + 4 * H * H,
               bih + 4 * H, bhh + 4 * H, hn + H, cn + H, bid, wid, lane, tid, sm);
    gbar();

    // ---- phase 2: att_fc1 + full-sequence scores + ctx reset (ht -> sm.xv) ----
    if (tid < 256) sm.xv[tid] = ((const float4*)(hn + H))[tid];
    __syncthreads();
    if (gw < HH2) {
        const float4* w4 = (const float4*)a1w + (size_t)gw * H4;
        float acc = 0.f;
        for (int k = 0; k < 8; k++) { int i = lane + 32 * k; acc += dot4(w4[i], sm.xv[i]); }
        acc = warpSum(acc);
        if (lane == 0) g_t1[gw] = tanhf(acc + a1b[gw]);
    } else {
        int s = gw - HH2;
        int slim = (S < SMAX) ? S : SMAX;
        if (s < slim) {
            const float4* e4 = (const float4*)(enc + (size_t)s * H);
            float acc = 0.f;
            for (int k = 0; k < 8; k++) { int i = lane + 32 * k; acc += dot4(e4[i], sm.xv[i]); }
            acc = warpSum(acc);
            if (lane == 0) g_sc[s] = acc;
        }
    }
    if (bid == NB - 1) { g_ctx[tid] = 0.f; g_ctx[tid + 512] = 0.f; }
    gbar();

    // ---- phase 3: redundant p + window softmax; distributed ctx ----
    {
        float part = g_t1[tid < HH2 ? tid : 0] * a2w[tid < HH2 ? tid : 0];
        if (tid >= HH2) part = 0.f;     // NT==512 so all active, but keep safe
        part = warpSum(part);
        if (lane == 0) sm.red[wid] = part;
        __syncthreads();
        if (tid == 0) {
            float s = a2b[0];
            #pragma unroll
            for (int i = 0; i < NWARP; i++) s += sm.red[i];
            float p = Sf * sigm(s);
            sm.p  = p;
            sm.ws = (int)rintf(fmaxf(p - 64.f, 0.f));
            sm.we = (int)rintf(fminf(p + 64.f, Sf - 1.f));
        }
        __syncthreads();
        int ws = sm.ws, we = sm.we;
        if (tid < WIN) {
            int idx = ws + tid;
            sm.sarr[tid] = (idx <= we) ? g_sc[min(idx, S - 1)] : NEG;
        }
        __syncthreads();
        if (tid < 32) {
            float m = NEG;
            for (int i = lane; i < WIN; i += 32) m = fmaxf(m, sm.sarr[i]);
            m = warpMax(m);
            float e = 0.f;
            for (int i = lane; i < WIN; i += 32) e += expf(sm.sarr[i] - m);
            e = warpSum(e);
            if (lane == 0) { sm.mx = m; sm.sum = e; }
        }
        __syncthreads();
        if (tid < WIN) {
            int idx = ws + tid;
            float a = expf(sm.sarr[tid] - sm.mx) / sm.sum;
            float gs = expf(((float)idx - sm.p) * (1.f / 2048.f));
            a = (idx <= we) ? a * gs : 0.f;
            sm.aarr[tid] = a;
            if (bid == 0) aout[tid] = a;
        }
        __syncthreads();
        if (bid < WIN) {
            float a = sm.aarr[bid];
            int idx = min(sm.ws + bid, S - 1);
            const float* er = enc + (size_t)idx * H;
            atomicAdd(&g_ctx[tid      ], a * er[tid      ]);
            atomicAdd(&g_ctx[tid + 512], a * er[tid + 512]);
        }
    }
    gbar();

    // ---- phase 4: fc1 (1024 rows x 2048), rows spread over blocks ----
    {
        int r = wid * NB + bid;
        if (r < H) {
            const float4* w4 = (const float4*)f1w + (size_t)r * (2 * H4);
            const float4* c4 = (const float4*)g_ctx;
            float acc = 0.f;
            for (int k = 0; k < 8; k++) { int i = lane + 32 * k; acc += dot4(w4[i      ], c4[i]); }
            for (int k = 0; k < 8; k++) { int i = lane + 32 * k; acc += dot4(w4[i + 256], sm.xv[i]); }
            acc = warpSum(acc);
            if (lane == 0) fco[r] = tanhf(acc + f1b[r]);
        }
    }
    gbar();

    // ---- phase 5: fc2 (32000 x 1024) + online block-partial (max, expsum) ----
    {
        if (tid < 256) sm.xv[tid] = ((const float4*)fco)[tid];
        __syncthreads();
        float mw = NEG, sw = 0.f;
        for (int r = gw; r < V; r += NWRP) {
            const float4* w4 = (const float4*)f2w + (size_t)r * H4;
            float acc = 0.f;
            for (int k = 0; k < 8; k++) { int i = lane + 32 * k; acc += dot4(w4[i], sm.xv[i]); }
            acc = warpSum(acc);
            if (lane == 0) {
                float v = acc + f2b[r];
                y[r] = v;
                float m2 = fmaxf(mw, v);
                sw = sw * expf(mw - m2) + expf(v - m2);
                mw = m2;
            }
        }
        if (lane == 0) { sm.mr[wid] = mw; sm.sr[wid] = sw; }
        __syncthreads();
        if (tid == 0) {
            float M = NEG, Ss = 0.f;
            #pragma unroll
            for (int i = 0; i < NWARP; i++) {
                float m2 = fmaxf(M, sm.mr[i]);
                Ss = Ss * expf(M - m2) + sm.sr[i] * expf(sm.mr[i] - m2);
                M = m2;
            }
            g_pm[bid] = M; g_ps[bid] = Ss;
        }
    }
    gbar();

    // ---- phase 6: combine block partials (fixed tree), subtract lse ----
    {
        if (tid < NB) { sm.mr[tid] = g_pm[tid]; sm.sr[tid] = g_ps[tid]; }
        else          { sm.mr[tid] = NEG;       sm.sr[tid] = 0.f; }
        __syncthreads();
        for (int off = 256; off > 0; off >>= 1) {
            if (tid < off) {
                float m1 = sm.mr[tid], m2 = sm.mr[tid + off];
                float m = fmaxf(m1, m2);
                sm.sr[tid] = sm.sr[tid] * expf(m1 - m) + sm.sr[tid + off] * expf(m2 - m);
                sm.mr[tid] = m;
            }
            __syncthreads();
        }
        float lse = sm.mr[0] + logf(sm.sr[0]);
        const int chunk = (V + NB - 1) / NB;    // 73
        int i = bid * chunk + tid;
        if (tid < chunk && i < V) y[i] -= lse;
    }
}

// ---------------- launch ----------------
extern "C" void kernel_launch(void* const* d_in, const int* in_sizes, int n_in,
                              void* d_out, int out_size)
{
    const float* enc  = (const float*)d_in[1];
    const int*   word = (const int*)  d_in[2];
    const float* h0   = (const float*)d_in[3];
    const float* c0   = (const float*)d_in[4];
    const float* emb  = (const float*)d_in[5];
    const float* wih  = (const float*)d_in[6];
    const float* whh  = (const float*)d_in[7];
    const float* bih  = (const float*)d_in[8];
    const float* bhh  = (const float*)d_in[9];
    const float* a1w  = (const float*)d_in[10];
    const float* a1b  = (const float*)d_in[11];
    const float* a2w  = (const float*)d_in[12];
    const float* a2b  = (const float*)d_in[13];
    const float* f1w  = (const float*)d_in[14];
    const float* f1b  = (const float*)d_in[15];
    const float* f2w  = (const float*)d_in[16];
    const float* f2b  = (const float*)d_in[17];

    int S = in_sizes[1] / H;

    decoder_mega<<<NB, NT>>>(enc, word, h0, c0, emb, wih, whh, bih, bhh,
                             a1w, a1b, a2w, a2b, f1w, f1b, f2w, f2b,
                             (float*)d_out, S);
}